// round 12
// baseline (speedup 1.0000x reference)
#include <cuda_runtime.h>
#include <cstdint>

// 2D Haar DWT, one level.
// Input:  x  (16,1,2048,2048) fp32
// Output: [ll | lh | hl | hh], each (16,1,1024,1024) fp32, concatenated.
//
// Thread t handles batch b, output row i, and FOUR output columns
// [4*q .. 4*q+3]: two float4 loads from each of input rows 2i, 2i+1
// (32B contiguous per row), one float4 streaming store per band.
// All index arithmetic in int32 (max element offset < 2^27).

static __device__ __forceinline__ float safef(float v) {
    return isfinite(v) ? v : 0.0f;
}

static __device__ __forceinline__ void haar2(
    float a, float b, float c, float d,
    float& ll, float& lh, float& hl, float& hh)
{
    a = safef(a); b = safef(b); c = safef(c); d = safef(d);
    const float h = 0.5f;
    ll = h * ( a + b + c + d);
    lh = h * (-a + b - c + d);
    hl = h * (-a - b + c + d);
    hh = h * ( a - b - c + d);
}

__global__ void __launch_bounds__(512) dwt2d_haar_kernel(
    const float* __restrict__ x, float* __restrict__ out)
{
    constexpr int W   = 2048;          // input width
    constexpr int Wo  = 1024;          // output width
    constexpr int Ho  = 1024;          // output height
    constexpr int QP  = Wo / 4;        // 256 quad-groups per output row
    constexpr int NB4 = (16 * Ho * Wo) / 4; // float4 elems per band = 4M

    int t = blockIdx.x * 512 + threadIdx.x;     // 0 .. 16*1024*256-1
    int q = t & (QP - 1);                        // quad index, 0..255
    int rest = t >> 8;
    int i = rest & (Ho - 1);                     // output row, 0..1023
    int b = rest >> 10;                          // batch, 0..15

    // input float4 row index: row (b*W + 2i) has W/4 = 512 float4's
    int in_row0 = (b * W + 2 * i) * (W / 4);     // max ~16.7M, fits int
    const float4* xi = reinterpret_cast<const float4*>(x);

    float4 r0a = xi[in_row0 + 2 * q];
    float4 r0b = xi[in_row0 + 2 * q + 1];
    float4 r1a = xi[in_row0 + (W / 4) + 2 * q];
    float4 r1b = xi[in_row0 + (W / 4) + 2 * q + 1];

    float4 ll, lh, hl, hh;
    haar2(r0a.x, r0a.y, r1a.x, r1a.y, ll.x, lh.x, hl.x, hh.x);
    haar2(r0a.z, r0a.w, r1a.z, r1a.w, ll.y, lh.y, hl.y, hh.y);
    haar2(r0b.x, r0b.y, r1b.x, r1b.y, ll.z, lh.z, hl.z, hh.z);
    haar2(r0b.z, r0b.w, r1b.z, r1b.w, ll.w, lh.w, hl.w, hh.w);

    // float4 offset within a band
    int o4 = (b * Ho + i) * (Wo / 4) + q;        // max 4M, fits int
    float4* po = reinterpret_cast<float4*>(out);

    __stcs(&po[o4],           ll);
    __stcs(&po[o4 + NB4],     lh);
    __stcs(&po[o4 + 2 * NB4], hl);
    __stcs(&po[o4 + 3 * NB4], hh);
}

extern "C" void kernel_launch(void* const* d_in, const int* in_sizes, int n_in,
                              void* d_out, int out_size)
{
    const float* x = (const float*)d_in[0];
    float* out = (float*)d_out;

    const int total_threads = 16 * 1024 * 256;   // 4,194,304
    const int block = 512;
    const int grid = total_threads / block;      // 8192

    dwt2d_haar_kernel<<<grid, block>>>(x, out);
}

// round 13
// speedup vs baseline: 1.0008x; 1.0008x over previous
#include <cuda_runtime.h>
#include <cstdint>

// 2D Haar DWT, one level.
// Input:  x  (16,1,2048,2048) fp32
// Output: [ll | lh | hl | hh], each (16,1,1024,1024) fp32, concatenated.
//
// Thread t handles batch b, output row i, and FOUR output columns
// [4*q .. 4*q+3]: two float4 loads from each of input rows 2i, 2i+1
// (32B contiguous per row), one float4 streaming store per band.
// All index arithmetic in int32 (max element offset < 2^27).

static __device__ __forceinline__ float safef(float v) {
    return isfinite(v) ? v : 0.0f;
}

static __device__ __forceinline__ void haar2(
    float a, float b, float c, float d,
    float& ll, float& lh, float& hl, float& hh)
{
    a = safef(a); b = safef(b); c = safef(c); d = safef(d);
    const float h = 0.5f;
    ll = h * ( a + b + c + d);
    lh = h * (-a + b - c + d);
    hl = h * (-a - b + c + d);
    hh = h * ( a - b - c + d);
}

__global__ void __launch_bounds__(512) dwt2d_haar_kernel(
    const float* __restrict__ x, float* __restrict__ out)
{
    constexpr int W   = 2048;          // input width
    constexpr int Wo  = 1024;          // output width
    constexpr int Ho  = 1024;          // output height
    constexpr int QP  = Wo / 4;        // 256 quad-groups per output row
    constexpr int NB4 = (16 * Ho * Wo) / 4; // float4 elems per band = 4M

    int t = blockIdx.x * 512 + threadIdx.x;     // 0 .. 16*1024*256-1
    int q = t & (QP - 1);                        // quad index, 0..255
    int rest = t >> 8;
    int i = rest & (Ho - 1);                     // output row, 0..1023
    int b = rest >> 10;                          // batch, 0..15

    // input float4 row index: row (b*W + 2i) has W/4 = 512 float4's
    int in_row0 = (b * W + 2 * i) * (W / 4);     // max ~16.7M, fits int
    const float4* xi = reinterpret_cast<const float4*>(x);

    float4 r0a = xi[in_row0 + 2 * q];
    float4 r0b = xi[in_row0 + 2 * q + 1];
    float4 r1a = xi[in_row0 + (W / 4) + 2 * q];
    float4 r1b = xi[in_row0 + (W / 4) + 2 * q + 1];

    float4 ll, lh, hl, hh;
    haar2(r0a.x, r0a.y, r1a.x, r1a.y, ll.x, lh.x, hl.x, hh.x);
    haar2(r0a.z, r0a.w, r1a.z, r1a.w, ll.y, lh.y, hl.y, hh.y);
    haar2(r0b.x, r0b.y, r1b.x, r1b.y, ll.z, lh.z, hl.z, hh.z);
    haar2(r0b.z, r0b.w, r1b.z, r1b.w, ll.w, lh.w, hl.w, hh.w);

    // float4 offset within a band
    int o4 = (b * Ho + i) * (Wo / 4) + q;        // max 4M, fits int
    float4* po = reinterpret_cast<float4*>(out);

    __stcs(&po[o4],           ll);
    __stcs(&po[o4 + NB4],     lh);
    __stcs(&po[o4 + 2 * NB4], hl);
    __stcs(&po[o4 + 3 * NB4], hh);
}

extern "C" void kernel_launch(void* const* d_in, const int* in_sizes, int n_in,
                              void* d_out, int out_size)
{
    const float* x = (const float*)d_in[0];
    float* out = (float*)d_out;

    const int total_threads = 16 * 1024 * 256;   // 4,194,304
    const int block = 512;
    const int grid = total_threads / block;      // 8192

    dwt2d_haar_kernel<<<grid, block>>>(x, out);
}

// round 14
// speedup vs baseline: 1.0078x; 1.0070x over previous
#include <cuda_runtime.h>
#include <cstdint>

// 2D Haar DWT, one level.
// Input:  x  (16,1,2048,2048) fp32
// Output: [ll | lh | hl | hh], each (16,1,1024,1024) fp32, concatenated.
//
// Thread t handles batch b, output row i, and FOUR output columns
// [4*q .. 4*q+3]: two float4 loads from each of input rows 2i, 2i+1
// (32B contiguous per row), one float4 streaming store per band.
// All index arithmetic in int32 (max element offset < 2^27).

static __device__ __forceinline__ float safef(float v) {
    return isfinite(v) ? v : 0.0f;
}

static __device__ __forceinline__ void haar2(
    float a, float b, float c, float d,
    float& ll, float& lh, float& hl, float& hh)
{
    a = safef(a); b = safef(b); c = safef(c); d = safef(d);
    const float h = 0.5f;
    ll = h * ( a + b + c + d);
    lh = h * (-a + b - c + d);
    hl = h * (-a - b + c + d);
    hh = h * ( a - b - c + d);
}

__global__ void __launch_bounds__(512) dwt2d_haar_kernel(
    const float* __restrict__ x, float* __restrict__ out)
{
    constexpr int W   = 2048;          // input width
    constexpr int Wo  = 1024;          // output width
    constexpr int Ho  = 1024;          // output height
    constexpr int QP  = Wo / 4;        // 256 quad-groups per output row
    constexpr int NB4 = (16 * Ho * Wo) / 4; // float4 elems per band = 4M

    int t = blockIdx.x * 512 + threadIdx.x;     // 0 .. 16*1024*256-1
    int q = t & (QP - 1);                        // quad index, 0..255
    int rest = t >> 8;
    int i = rest & (Ho - 1);                     // output row, 0..1023
    int b = rest >> 10;                          // batch, 0..15

    // input float4 row index: row (b*W + 2i) has W/4 = 512 float4's
    int in_row0 = (b * W + 2 * i) * (W / 4);     // max ~16.7M, fits int
    const float4* xi = reinterpret_cast<const float4*>(x);

    float4 r0a = xi[in_row0 + 2 * q];
    float4 r0b = xi[in_row0 + 2 * q + 1];
    float4 r1a = xi[in_row0 + (W / 4) + 2 * q];
    float4 r1b = xi[in_row0 + (W / 4) + 2 * q + 1];

    float4 ll, lh, hl, hh;
    haar2(r0a.x, r0a.y, r1a.x, r1a.y, ll.x, lh.x, hl.x, hh.x);
    haar2(r0a.z, r0a.w, r1a.z, r1a.w, ll.y, lh.y, hl.y, hh.y);
    haar2(r0b.x, r0b.y, r1b.x, r1b.y, ll.z, lh.z, hl.z, hh.z);
    haar2(r0b.z, r0b.w, r1b.z, r1b.w, ll.w, lh.w, hl.w, hh.w);

    // float4 offset within a band
    int o4 = (b * Ho + i) * (Wo / 4) + q;        // max 4M, fits int
    float4* po = reinterpret_cast<float4*>(out);

    __stcs(&po[o4],           ll);
    __stcs(&po[o4 + NB4],     lh);
    __stcs(&po[o4 + 2 * NB4], hl);
    __stcs(&po[o4 + 3 * NB4], hh);
}

extern "C" void kernel_launch(void* const* d_in, const int* in_sizes, int n_in,
                              void* d_out, int out_size)
{
    const float* x = (const float*)d_in[0];
    float* out = (float*)d_out;

    const int total_threads = 16 * 1024 * 256;   // 4,194,304
    const int block = 512;
    const int grid = total_threads / block;      // 8192

    dwt2d_haar_kernel<<<grid, block>>>(x, out);
}